// round 7
// baseline (speedup 1.0000x reference)
#include <cuda_runtime.h>

#define BATCH 512
#define SEQ   200
#define TT    10
#define EMB   25
#define HH    64
#define G3    192          // 3*H
#define BT    7            // batch rows per GRU block
#define BLK_PER_DIR 74     // ceil(512/7)

// ---------------- scratch (static device memory; no allocation) ----------------
__device__ float g_xpf[SEQ * BATCH * G3];   // [s][b][192] forward input proj
__device__ float g_xpb[SEQ * BATCH * G3];   // [s][b][192] backward input proj
__device__ float g_hsf[SEQ * BATCH * HH];   // [s][b][64]
__device__ float g_hsb[SEQ * BATCH * HH];   // [s][b][64] (stored at original s)
__device__ float g_hT [BATCH * HH];
__device__ float g_mask[SEQ * BATCH];       // [s][b] step mask as float

// ---------------- f32x2 helpers ----------------
__device__ __forceinline__ unsigned long long pack2(float lo, float hi) {
    unsigned long long r;
    asm("mov.b64 %0, {%1, %2};" : "=l"(r) : "r"(__float_as_uint(lo)), "r"(__float_as_uint(hi)));
    return r;
}
__device__ __forceinline__ void unpack2(unsigned long long v, float& lo, float& hi) {
    unsigned int a, b;
    asm("mov.b64 {%0, %1}, %2;" : "=r"(a), "=r"(b) : "l"(v));
    lo = __uint_as_float(a); hi = __uint_as_float(b);
}
__device__ __forceinline__ unsigned long long fma2(unsigned long long a, unsigned long long b,
                                                   unsigned long long c) {
    unsigned long long d;
    asm("fma.rn.f32x2 %0, %1, %2, %3;" : "=l"(d) : "l"(a), "l"(b), "l"(c));
    return d;
}

// accurate-enough fast activations (ex2.approx based, ~1e-6 rel err)
__device__ __forceinline__ float sigx(float x) {
    return __fdividef(1.0f, 1.0f + __expf(-x));
}
__device__ __forceinline__ float tanhx(float x) {
    return fmaf(2.0f, sigx(2.0f * x), -1.0f);
}

// =====================================================================
// Kernel A: embedding gather + masked mean + both input projections.
//   384 threads: gather phase all threads; projection phase all threads:
//   c = tid%192, row-half = tid/192 (16 rows each). W_f/W_b packed f32x2.
// =====================================================================
__global__ __launch_bounds__(384) void kA(const int* __restrict__ inp,
                                          const float* __restrict__ emb,
                                          const float* __restrict__ Wf,
                                          const float* __restrict__ bf,
                                          const float* __restrict__ Wb,
                                          const float* __restrict__ bb) {
    __shared__ __align__(16) float2 xs2[32][EMB];   // x duplicated (x,x)
    const int tid = threadIdx.x;
    const int base = blockIdx.x * 32;

    // gather + masked mean (800 items over 384 threads)
    for (int o = tid; o < 32 * EMB; o += 384) {
        int r = o / EMB, e = o - r * EMB;
        const int* ip = inp + (size_t)(base + r) * TT;
        float sum = 0.0f; int cnt = 0;
#pragma unroll
        for (int t = 0; t < TT; t++) {
            int idx = ip[t];
            if (idx != 0) { sum += emb[(size_t)idx * EMB + e]; cnt++; }
        }
        float x = sum / (float)(cnt > 0 ? cnt : 1);
        xs2[r][e] = make_float2(x, x);
    }
    // step mask
    if (tid < 32) {
        int row = base + tid;
        int b = row / SEQ, s = row - b * SEQ;
        g_mask[s * BATCH + b] = (inp[(size_t)row * TT] != 0) ? 1.0f : 0.0f;
    }
    __syncthreads();

    {
        const int c = tid % G3;
        const int half = tid / G3;            // 0/1 -> rows [0,16) / [16,32)
        unsigned long long w2[EMB];           // (W_f[k][c], W_b[k][c])
#pragma unroll
        for (int k = 0; k < EMB; k++) w2[k] = pack2(Wf[k * G3 + c], Wb[k * G3 + c]);
        const unsigned long long bias2 = pack2(bf[c], bb[c]);   // row 0 of b_f/b_b
#pragma unroll 4
        for (int rr = 0; rr < 16; rr++) {
            const int r = half * 16 + rr;
            const unsigned long long* xp = (const unsigned long long*)xs2[r];
            unsigned long long a0 = bias2;
            unsigned long long a1 = pack2(0.0f, 0.0f);
#pragma unroll
            for (int k = 0; k + 1 < EMB; k += 2) {
                a0 = fma2(xp[k], w2[k], a0);
                a1 = fma2(xp[k + 1], w2[k + 1], a1);
            }
            a0 = fma2(xp[EMB - 1], w2[EMB - 1], a0);   // EMB=25 odd tail
            float l0, h0, l1, h1;
            unpack2(a0, l0, h0); unpack2(a1, l1, h1);
            int row = base + r;
            int b = row / SEQ, s = row - b * SEQ;
            size_t off = ((size_t)s * BATCH + b) * G3 + c;
            g_xpf[off] = l0 + l1;
            g_xpb[off] = h0 + h1;
        }
    }
}

// =====================================================================
// Kernel B: bidirectional GRU scans. grid = 148 blocks, 448 threads.
//   Matvec: tid<384 = 192 cols x 2 k-halves; U half-column in 16 packed
//   pairs (32 regs, no spill). All 7 rows per thread (uniform balance).
//   Partials srec0/srec1 summed by gate threads -> no extra barrier.
//   Gates: all 448 threads = (row 0..6, j 0..63).
// =====================================================================
__global__ __launch_bounds__(448, 1) void kB(const float* __restrict__ Uf,
                                             const float* __restrict__ bf,
                                             const float* __restrict__ Ub,
                                             const float* __restrict__ bb) {
    __shared__ __align__(16) float sh[BT][HH];
    __shared__ __align__(16) float srec0[BT][G3];
    __shared__ __align__(16) float srec1[BT][G3];

    const int tid = threadIdx.x;
    const int dir = blockIdx.x / BLK_PER_DIR;
    const int tile = blockIdx.x - dir * BLK_PER_DIR;
    const int b0 = tile * BT;

    const float* U    = dir ? Ub : Uf;
    const float* brec = (dir ? bb : bf) + G3;        // recurrent bias row
    const float* xp   = dir ? g_xpb : g_xpf;
    float* hs         = dir ? g_hsb : g_hsf;

    const bool mv = tid < 2 * G3;           // 384 matvec threads
    const int c  = tid % G3;
    const int kg = tid / G3;                // k-half: 0 -> k[0,32), 1 -> k[32,64)
    const int k0 = kg * 32;

    unsigned long long u2[16];              // (U[k0+2t][c], U[k0+2t+1][c])
    unsigned long long bias2 = pack2(0.0f, 0.0f);
    float* srec_my = kg ? &srec1[0][0] : &srec0[0][0];
    if (mv) {
#pragma unroll
        for (int t = 0; t < 16; t++)
            u2[t] = pack2(U[(k0 + 2 * t) * G3 + c], U[(k0 + 2 * t + 1) * G3 + c]);
        if (kg == 0) bias2 = pack2(brec[c], 0.0f);
    }

    const int gr = tid / HH, j = tid % HH;  // gate role (all 448 threads)
    const int bb_ = b0 + gr;
    const bool gv = bb_ < BATCH;

    sh[gr][j] = 0.0f;
    __syncthreads();

    for (int si = 0; si < SEQ; si++) {
        const int s = dir ? (SEQ - 1 - si) : si;

        // prefetch xp + mask (independent of h; hides latency behind matvec)
        float xz = 0.0f, xr = 0.0f, xh = 0.0f, m = 0.0f;
        if (gv) {
            size_t o = ((size_t)s * BATCH + bb_) * G3 + j;
            xz = xp[o]; xr = xp[o + HH]; xh = xp[o + 2 * HH];
            m = g_mask[s * BATCH + bb_];
        }

        if (mv) {
#pragma unroll
            for (int r = 0; r < BT; r++) {
                const ulonglong2* hp = (const ulonglong2*)(&sh[r][k0]);
                unsigned long long a0 = bias2;
                unsigned long long a1 = pack2(0.0f, 0.0f);
#pragma unroll
                for (int t = 0; t < 8; t++) {
                    ulonglong2 hv = hp[t];          // 4 h values (2 packed pairs)
                    a0 = fma2(hv.x, u2[2 * t], a0);
                    a1 = fma2(hv.y, u2[2 * t + 1], a1);
                }
                float l0, h0, l1, h1;
                unpack2(a0, l0, h0); unpack2(a1, l1, h1);
                srec_my[r * G3 + c] = (l0 + h0) + (l1 + h1);
            }
        }
        __syncthreads();

        if (gv) {
            float rz = srec0[gr][j]          + srec1[gr][j];
            float rr = srec0[gr][HH + j]     + srec1[gr][HH + j];
            float rh = srec0[gr][2 * HH + j] + srec1[gr][2 * HH + j];
            float z   = sigx(xz + rz);
            float rg  = sigx(xr + rr);
            float hhv = tanhx(xh + rg * rh);
            float hold = sh[gr][j];
            float hn = z * hold + (1.0f - z) * hhv;
            hn = hold + m * (hn - hold);            // masked update
            sh[gr][j] = hn;
            hs[((size_t)s * BATCH + bb_) * HH + j] = hn;
        }
        __syncthreads();
    }

    if (dir == 0 && gv) g_hT[bb_ * HH + j] = sh[gr][j];
}

// =====================================================================
// Kernel C: attention. grid = 512 (one block per batch), 256 threads.
//   keys matvec: thread = (s-lane, k-half, j); W_k half-column in regs,
//   out broadcast from SMEM via LDS.128 (2 packed pairs per load).
// =====================================================================
__global__ __launch_bounds__(256) void kC(const float* __restrict__ Wk,
                                          const float* __restrict__ bk,
                                          const float* __restrict__ Wq,
                                          const float* __restrict__ bq,
                                          const float* __restrict__ We,
                                          const float* __restrict__ be,
                                          float* __restrict__ out) {
    __shared__ __align__(16) float sout[8][2 * HH];   // 8 timesteps of concat out
    __shared__ float spp[8][2][HH];                   // partial keys per k-half
    __shared__ float sq[HH], sbk[HH], sWe[HH];
    __shared__ float se[SEQ];
    __shared__ float sinv;

    const int tid = threadIdx.x;
    const int b = blockIdx.x;

    const int sl = tid / 128;            // 0/1 : handles s_local [sl*4, sl*4+4)
    const int inner = tid & 127;
    const int kh = inner / HH;           // 0/1 : k in [kh*64, kh*64+64)
    const int j = inner & (HH - 1);

    unsigned long long w2[32];           // (W_k[k][j], W_k[k+1][j]) for my half
#pragma unroll
    for (int t = 0; t < 32; t++)
        w2[t] = pack2(Wk[(kh * HH + 2 * t) * HH + j], Wk[(kh * HH + 2 * t + 1) * HH + j]);

    if (tid < HH) {
        float q = bq[tid];
#pragma unroll
        for (int k = 0; k < HH; k++) q += g_hT[b * HH + k] * Wq[k * HH + tid];
        sq[tid] = q;
        sbk[tid] = bk[tid];
        sWe[tid] = We[tid];
    }
    __syncthreads();

    const float be0 = be[0];

    for (int ch = 0; ch < SEQ / 8; ch++) {
        const int s0 = ch * 8;
        // stage out[s0..s0+8) into SMEM
        for (int o = tid; o < 8 * 2 * HH; o += 256) {
            int sl_ = o >> 7, k = o & 127;
            size_t off = ((size_t)(s0 + sl_) * BATCH + b) * HH;
            sout[sl_][k] = (k < HH) ? g_hsf[off + k] : g_hsb[off + (k - HH)];
        }
        __syncthreads();

        float p[4];
#pragma unroll
        for (int ss = 0; ss < 4; ss++) {
            const ulonglong2* op = (const ulonglong2*)(&sout[sl * 4 + ss][kh * HH]);
            unsigned long long a0 = pack2(0.0f, 0.0f), a1 = pack2(0.0f, 0.0f);
#pragma unroll
            for (int t = 0; t < 16; t++) {
                ulonglong2 ov = op[t];
                a0 = fma2(ov.x, w2[2 * t],     a0);
                a1 = fma2(ov.y, w2[2 * t + 1], a1);
            }
            float l0, h0, l1, h1;
            unpack2(a0, l0, h0); unpack2(a1, l1, h1);
            p[ss] = (l0 + h0) + (l1 + h1);
        }
#pragma unroll
        for (int ss = 0; ss < 4; ss++) spp[sl * 4 + ss][kh][j] = p[ss];
        __syncthreads();

        // e_s = tanh(key + q) . We + be  (one warp per timestep)
        {
            const int sidx = tid / 32, lane = tid & 31;
            float acc = 0.0f;
#pragma unroll
            for (int h = 0; h < 2; h++) {
                int jj = lane + h * 32;
                float key = spp[sidx][0][jj] + spp[sidx][1][jj] + sbk[jj];
                acc += tanhx(key + sq[jj]) * sWe[jj];
            }
#pragma unroll
            for (int off = 16; off > 0; off >>= 1)
                acc += __shfl_xor_sync(0xFFFFFFFFu, acc, off);
            if (lane == 0) {
                int s = s0 + sidx;
                float m = g_mask[s * BATCH + b];
                se[s] = acc + be0 + (1.0f - m) * (-1e9f);
            }
        }
        __syncthreads();
    }

    // softmax over S (one warp)
    if (tid < 32) {
        float mx = -1e30f;
        for (int s = tid; s < SEQ; s += 32) mx = fmaxf(mx, se[s]);
#pragma unroll
        for (int off = 16; off > 0; off >>= 1)
            mx = fmaxf(mx, __shfl_xor_sync(0xFFFFFFFFu, mx, off));
        float sum = 0.0f;
        for (int s = tid; s < SEQ; s += 32) {
            float pz = __expf(se[s] - mx);
            se[s] = pz; sum += pz;
        }
#pragma unroll
        for (int off = 16; off > 0; off >>= 1)
            sum += __shfl_xor_sync(0xFFFFFFFFu, sum, off);
        if (tid == 0) sinv = __fdividef(1.0f, sum);
    }
    __syncthreads();

    // context = sum_s w_s * out_s
    if (tid < 2 * HH) {
        const int k = tid;
        const float* src = (k < HH) ? (g_hsf + (size_t)b * HH + k)
                                    : (g_hsb + (size_t)b * HH + (k - HH));
        float ctx = 0.0f;
#pragma unroll 4
        for (int s = 0; s < SEQ; s++)
            ctx += se[s] * src[(size_t)s * (BATCH * HH)];
        out[b * (2 * HH) + k] = ctx * sinv;
    }
}

// =====================================================================
extern "C" void kernel_launch(void* const* d_in, const int* in_sizes, int n_in,
                              void* d_out, int out_size) {
    const int*   inp = (const int*)d_in[0];
    const float* emb = (const float*)d_in[1];
    const float* Wf  = (const float*)d_in[2];
    const float* Uf  = (const float*)d_in[3];
    const float* bf  = (const float*)d_in[4];
    const float* Wb  = (const float*)d_in[5];
    const float* Ub  = (const float*)d_in[6];
    const float* bb  = (const float*)d_in[7];
    const float* Wk  = (const float*)d_in[8];
    const float* bk  = (const float*)d_in[9];
    const float* Wq  = (const float*)d_in[10];
    const float* bq  = (const float*)d_in[11];
    const float* We  = (const float*)d_in[12];
    const float* be  = (const float*)d_in[13];
    float* out = (float*)d_out;

    kA<<<(BATCH * SEQ) / 32, 384>>>(inp, emb, Wf, bf, Wb, bb);
    kB<<<2 * BLK_PER_DIR, 448>>>(Uf, bf, Ub, bb);
    kC<<<BATCH, 256>>>(Wk, bk, Wq, bq, We, be, out);
}

// round 8
// speedup vs baseline: 1.6734x; 1.6734x over previous
#include <cuda_runtime.h>

#define BATCH 512
#define SEQ   200
#define TT    10
#define EMB   25
#define EMB_P 28           // padded x row in smem (8B-aligned pair loads)
#define HH    64
#define G3    192          // 3*H
#define BT    7            // batch rows per GRU block
#define BLK_PER_DIR 74     // ceil(512/7)

// ---------------- scratch (static device memory; no allocation) ----------------
__device__ float g_x  [SEQ * BATCH * EMB];  // [s][b][25] pooled embeddings (10MB, L2-resident)
__device__ float g_hsf[SEQ * BATCH * HH];   // [s][b][64]
__device__ float g_hsb[SEQ * BATCH * HH];   // [s][b][64] (stored at original s)
__device__ float g_hT [BATCH * HH];
__device__ float g_mask[SEQ * BATCH];       // [s][b] step mask as float

// ---------------- f32x2 helpers ----------------
__device__ __forceinline__ unsigned long long pack2(float lo, float hi) {
    unsigned long long r;
    asm("mov.b64 %0, {%1, %2};" : "=l"(r) : "r"(__float_as_uint(lo)), "r"(__float_as_uint(hi)));
    return r;
}
__device__ __forceinline__ void unpack2(unsigned long long v, float& lo, float& hi) {
    unsigned int a, b;
    asm("mov.b64 {%0, %1}, %2;" : "=r"(a), "=r"(b) : "l"(v));
    lo = __uint_as_float(a); hi = __uint_as_float(b);
}
__device__ __forceinline__ unsigned long long fma2(unsigned long long a, unsigned long long b,
                                                   unsigned long long c) {
    unsigned long long d;
    asm("fma.rn.f32x2 %0, %1, %2, %3;" : "=l"(d) : "l"(a), "l"(b), "l"(c));
    return d;
}

// fast activations (ex2.approx based, ~1e-6 rel err)
__device__ __forceinline__ float sigx(float x) {
    return __fdividef(1.0f, 1.0f + __expf(-x));
}
__device__ __forceinline__ float tanhx(float x) {
    return fmaf(2.0f, sigx(2.0f * x), -1.0f);
}

// =====================================================================
// Kernel A: embedding gather + masked mean only (projection moved to kB).
//   32 rows per block, 256 threads.
// =====================================================================
__global__ __launch_bounds__(256) void kA(const int* __restrict__ inp,
                                          const float* __restrict__ emb) {
    const int tid = threadIdx.x;
    const int base = blockIdx.x * 32;

    for (int o = tid; o < 32 * EMB; o += 256) {
        int r = o / EMB, e = o - r * EMB;
        const int* ip = inp + (size_t)(base + r) * TT;
        float sum = 0.0f; int cnt = 0;
#pragma unroll
        for (int t = 0; t < TT; t++) {
            int idx = ip[t];
            if (idx != 0) { sum += emb[(size_t)idx * EMB + e]; cnt++; }
        }
        int row = base + r;
        int b = row / SEQ, s = row - b * SEQ;
        g_x[((size_t)s * BATCH + b) * EMB + e] = sum / (float)(cnt > 0 ? cnt : 1);
    }
    if (tid < 32) {
        int row = base + tid;
        int b = row / SEQ, s = row - b * SEQ;
        g_mask[s * BATCH + b] = (inp[(size_t)row * TT] != 0) ? 1.0f : 0.0f;
    }
}

// =====================================================================
// Kernel B: bidirectional GRU with fused input projection.
//   grid = 148 (1 wave), 448 threads.
//   Matvec (tid<384): c = tid%192, k-half kg = tid/192.
//     h-part: U half-column in 16 packed pairs (32 regs), LDS.128 on sh.
//     x-part: W e-half in 6 packed pairs (+1 scalar tail for kg=1),
//             x staged in SMEM double buffer, prefetched 1 step ahead (L2 hit).
//   Gate chunks z/r: x and h parts share one accumulator (additive).
//   Gate chunk h:    kept separate (srec vs sx) since hh = tanh(xh + r*rh).
//   Gates: all 448 threads = (row 0..6, j 0..63).
// =====================================================================
__global__ __launch_bounds__(448, 1) void kB(const float* __restrict__ Uf,
                                             const float* __restrict__ bf,
                                             const float* __restrict__ Ub,
                                             const float* __restrict__ bb,
                                             const float* __restrict__ Wf,
                                             const float* __restrict__ Wb) {
    __shared__ __align__(16) float sh[BT][HH];
    __shared__ __align__(16) float srec0[BT][G3];
    __shared__ __align__(16) float srec1[BT][G3];
    __shared__ __align__(16) float sx0[BT][HH];
    __shared__ __align__(16) float sx1[BT][HH];
    __shared__ __align__(16) float xbuf[2][BT][EMB_P];

    const int tid = threadIdx.x;
    const int dir = blockIdx.x / BLK_PER_DIR;
    const int tile = blockIdx.x - dir * BLK_PER_DIR;
    const int b0 = tile * BT;

    const float* U   = dir ? Ub : Uf;
    const float* W   = dir ? Wb : Wf;
    const float* bia = dir ? bb : bf;      // [2][192]: row0 input bias, row1 recurrent bias
    float* hs        = dir ? g_hsb : g_hsf;

    const bool mv = tid < 2 * G3;           // 384 matvec threads
    const int c  = tid % G3;
    const int kg = tid / G3;                // k-half: 0 -> k[0,32), 1 -> k[32,64)
    const int k0 = kg * 32;
    const int chunk = c >> 6;               // 0:z 1:r 2:h
    const int e0 = kg ? 12 : 0;             // x e-range start

    unsigned long long u2[16];              // (U[k0+2t][c], U[k0+2t+1][c])
    unsigned long long wx2[6];              // (W[e0+2t][c], W[e0+2t+1][c])
    float wtail = 0.0f;
    unsigned long long hbias2 = pack2(0.0f, 0.0f);
    unsigned long long xbias2 = pack2(0.0f, 0.0f);
    float* srec_my = kg ? &srec1[0][0] : &srec0[0][0];
    float* sx_my   = kg ? &sx1[0][0]   : &sx0[0][0];
    if (mv) {
#pragma unroll
        for (int t = 0; t < 16; t++)
            u2[t] = pack2(U[(k0 + 2 * t) * G3 + c], U[(k0 + 2 * t + 1) * G3 + c]);
#pragma unroll
        for (int t = 0; t < 6; t++)
            wx2[t] = pack2(W[(e0 + 2 * t) * G3 + c], W[(e0 + 2 * t + 1) * G3 + c]);
        if (kg) wtail = W[24 * G3 + c];
        if (kg == 0) {
            hbias2 = pack2(bia[G3 + c], 0.0f);   // recurrent bias -> h accumulator
            xbias2 = pack2(bia[c], 0.0f);        // input bias     -> x accumulator
        }
    }

    const int gr = tid / HH, j = tid % HH;  // gate role (all 448 threads)
    const int bb_ = b0 + gr;
    const bool gv = bb_ < BATCH;

    sh[gr][j] = 0.0f;

    // prologue: stage x for the first step
    {
        const int s0 = dir ? (SEQ - 1) : 0;
        if (tid < BT * EMB) {
            int r = tid / EMB, e = tid - r * EMB;
            xbuf[0][r][e] = (b0 + r < BATCH)
                ? g_x[((size_t)s0 * BATCH + (b0 + r)) * EMB + e] : 0.0f;
        }
    }
    __syncthreads();

    for (int si = 0; si < SEQ; si++) {
        const int s = dir ? (SEQ - 1 - si) : si;
        const int cur = si & 1, nxt = cur ^ 1;

        // prefetch next step's x (L2-resident) + this step's mask
        float xpre = 0.0f; int pr = 0, pe = 0; bool pv = false;
        if (tid < BT * EMB && si + 1 < SEQ) {
            pr = tid / EMB; pe = tid - pr * EMB;
            const int sn = dir ? (s - 1) : (s + 1);
            if (b0 + pr < BATCH)
                xpre = g_x[((size_t)sn * BATCH + (b0 + pr)) * EMB + pe];
            pv = true;
        }
        float m = 0.0f;
        if (gv) m = g_mask[s * BATCH + bb_];

        if (mv) {
#pragma unroll
            for (int r = 0; r < BT; r++) {
                // h part: 32 k-values via 8 LDS.128 + 16 fma2
                const ulonglong2* hp = (const ulonglong2*)(&sh[r][k0]);
                unsigned long long a0 = hbias2, a1 = pack2(0.0f, 0.0f);
#pragma unroll
                for (int t = 0; t < 8; t++) {
                    ulonglong2 hv = hp[t];
                    a0 = fma2(hv.x, u2[2 * t],     a0);
                    a1 = fma2(hv.y, u2[2 * t + 1], a1);
                }
                // x part: 12 e-values (pairs) + tail
                const unsigned long long* xp =
                    (const unsigned long long*)(&xbuf[cur][r][e0]);
                unsigned long long c0 = xbias2, c1 = pack2(0.0f, 0.0f);
#pragma unroll
                for (int t = 0; t < 6; t += 2) {
                    c0 = fma2(xp[t],     wx2[t],     c0);
                    c1 = fma2(xp[t + 1], wx2[t + 1], c1);
                }
                float l0, h0, l1, h1;
                unpack2(a0, l0, h0); unpack2(a1, l1, h1);
                float hsum = (l0 + h0) + (l1 + h1);
                unpack2(c0, l0, h0); unpack2(c1, l1, h1);
                float xsum = (l0 + h0) + (l1 + h1);
                if (kg) xsum = fmaf(xbuf[cur][r][24], wtail, xsum);

                if (chunk == 2) {                 // h gate: keep parts separate
                    srec_my[r * G3 + c] = hsum;
                    sx_my[r * HH + (c - 2 * HH)] = xsum;
                } else {                           // z/r gates: additive
                    srec_my[r * G3 + c] = hsum + xsum;
                }
            }
        }
        if (pv) xbuf[nxt][pr][pe] = xpre;
        __syncthreads();

        if (gv) {
            float az = srec0[gr][j]          + srec1[gr][j];
            float ar = srec0[gr][HH + j]     + srec1[gr][HH + j];
            float rh = srec0[gr][2 * HH + j] + srec1[gr][2 * HH + j];
            float xh = sx0[gr][j]            + sx1[gr][j];
            float z   = sigx(az);
            float rg  = sigx(ar);
            float hhv = tanhx(xh + rg * rh);
            float hold = sh[gr][j];
            float hn = z * hold + (1.0f - z) * hhv;
            hn = hold + m * (hn - hold);            // masked update
            sh[gr][j] = hn;
            hs[((size_t)s * BATCH + bb_) * HH + j] = hn;
        }
        __syncthreads();
    }

    if (dir == 0 && gv) g_hT[bb_ * HH + j] = sh[gr][j];
}

// =====================================================================
// Kernel C: attention. grid = 512 (one block per batch), 256 threads.
// =====================================================================
__global__ __launch_bounds__(256) void kC(const float* __restrict__ Wk,
                                          const float* __restrict__ bk,
                                          const float* __restrict__ Wq,
                                          const float* __restrict__ bq,
                                          const float* __restrict__ We,
                                          const float* __restrict__ be,
                                          float* __restrict__ out) {
    __shared__ __align__(16) float sout[8][2 * HH];   // 8 timesteps of concat out
    __shared__ float spp[8][2][HH];                   // partial keys per k-half
    __shared__ float sq[HH], sbk[HH], sWe[HH];
    __shared__ float se[SEQ];
    __shared__ float sinv;

    const int tid = threadIdx.x;
    const int b = blockIdx.x;

    const int sl = tid / 128;            // 0/1 : handles s_local [sl*4, sl*4+4)
    const int inner = tid & 127;
    const int kh = inner / HH;           // 0/1 : k in [kh*64, kh*64+64)
    const int j = inner & (HH - 1);

    unsigned long long w2[32];           // (W_k[k][j], W_k[k+1][j]) for my half
#pragma unroll
    for (int t = 0; t < 32; t++)
        w2[t] = pack2(Wk[(kh * HH + 2 * t) * HH + j], Wk[(kh * HH + 2 * t + 1) * HH + j]);

    if (tid < HH) {
        float q = bq[tid];
#pragma unroll
        for (int k = 0; k < HH; k++) q += g_hT[b * HH + k] * Wq[k * HH + tid];
        sq[tid] = q;
        sbk[tid] = bk[tid];
        sWe[tid] = We[tid];
    }
    __syncthreads();

    const float be0 = be[0];

    for (int ch = 0; ch < SEQ / 8; ch++) {
        const int s0 = ch * 8;
        for (int o = tid; o < 8 * 2 * HH; o += 256) {
            int sl_ = o >> 7, k = o & 127;
            size_t off = ((size_t)(s0 + sl_) * BATCH + b) * HH;
            sout[sl_][k] = (k < HH) ? g_hsf[off + k] : g_hsb[off + (k - HH)];
        }
        __syncthreads();

        float p[4];
#pragma unroll
        for (int ss = 0; ss < 4; ss++) {
            const ulonglong2* op = (const ulonglong2*)(&sout[sl * 4 + ss][kh * HH]);
            unsigned long long a0 = pack2(0.0f, 0.0f), a1 = pack2(0.0f, 0.0f);
#pragma unroll
            for (int t = 0; t < 16; t++) {
                ulonglong2 ov = op[t];
                a0 = fma2(ov.x, w2[2 * t],     a0);
                a1 = fma2(ov.y, w2[2 * t + 1], a1);
            }
            float l0, h0, l1, h1;
            unpack2(a0, l0, h0); unpack2(a1, l1, h1);
            p[ss] = (l0 + h0) + (l1 + h1);
        }
#pragma unroll
        for (int ss = 0; ss < 4; ss++) spp[sl * 4 + ss][kh][j] = p[ss];
        __syncthreads();

        {
            const int sidx = tid / 32, lane = tid & 31;
            float acc = 0.0f;
#pragma unroll
            for (int h = 0; h < 2; h++) {
                int jj = lane + h * 32;
                float key = spp[sidx][0][jj] + spp[sidx][1][jj] + sbk[jj];
                acc += tanhx(key + sq[jj]) * sWe[jj];
            }
#pragma unroll
            for (int off = 16; off > 0; off >>= 1)
                acc += __shfl_xor_sync(0xFFFFFFFFu, acc, off);
            if (lane == 0) {
                int s = s0 + sidx;
                float m = g_mask[s * BATCH + b];
                se[s] = acc + be0 + (1.0f - m) * (-1e9f);
            }
        }
        __syncthreads();
    }

    if (tid < 32) {
        float mx = -1e30f;
        for (int s = tid; s < SEQ; s += 32) mx = fmaxf(mx, se[s]);
#pragma unroll
        for (int off = 16; off > 0; off >>= 1)
            mx = fmaxf(mx, __shfl_xor_sync(0xFFFFFFFFu, mx, off));
        float sum = 0.0f;
        for (int s = tid; s < SEQ; s += 32) {
            float pz = __expf(se[s] - mx);
            se[s] = pz; sum += pz;
        }
#pragma unroll
        for (int off = 16; off > 0; off >>= 1)
            sum += __shfl_xor_sync(0xFFFFFFFFu, sum, off);
        if (tid == 0) sinv = __fdividef(1.0f, sum);
    }
    __syncthreads();

    if (tid < 2 * HH) {
        const int k = tid;
        const float* src = (k < HH) ? (g_hsf + (size_t)b * HH + k)
                                    : (g_hsb + (size_t)b * HH + (k - HH));
        float ctx = 0.0f;
#pragma unroll 4
        for (int s = 0; s < SEQ; s++)
            ctx += se[s] * src[(size_t)s * (BATCH * HH)];
        out[b * (2 * HH) + k] = ctx * sinv;
    }
}

// =====================================================================
extern "C" void kernel_launch(void* const* d_in, const int* in_sizes, int n_in,
                              void* d_out, int out_size) {
    const int*   inp = (const int*)d_in[0];
    const float* emb = (const float*)d_in[1];
    const float* Wf  = (const float*)d_in[2];
    const float* Uf  = (const float*)d_in[3];
    const float* bf  = (const float*)d_in[4];
    const float* Wb  = (const float*)d_in[5];
    const float* Ub  = (const float*)d_in[6];
    const float* bb  = (const float*)d_in[7];
    const float* Wk  = (const float*)d_in[8];
    const float* bk  = (const float*)d_in[9];
    const float* Wq  = (const float*)d_in[10];
    const float* bq  = (const float*)d_in[11];
    const float* We  = (const float*)d_in[12];
    const float* be  = (const float*)d_in[13];
    float* out = (float*)d_out;

    kA<<<(BATCH * SEQ) / 32, 256>>>(inp, emb);
    kB<<<2 * BLK_PER_DIR, 448>>>(Uf, bf, Ub, bb, Wf, Wb);
    kC<<<BATCH, 256>>>(Wk, bk, Wq, bq, We, be, out);
}